// round 1
// baseline (speedup 1.0000x reference)
#include <cuda_runtime.h>

#define NSEQ   2048
#define EMB    1024
#define NH     16
#define HD     64
#define BATCH  2
#define MROWS  (BATCH * NSEQ)   // 4096
#define SCALE  0.125f           // 1/sqrt(64)

// Scratch (allocation-free rule: __device__ globals). 4 x 16MB = 64MB.
__device__ float g_q[MROWS * EMB];
__device__ float g_k[MROWS * EMB];
__device__ float g_v[MROWS * EMB];
__device__ float g_a[MROWS * EMB];

// ---------------------------------------------------------------------------
// GEMM: C[4096,1024] = A[4096,1024] @ W[1024,1024]^T + bias
// 128x128 tile, BK=8, 256 threads, 8x8 per thread.
// ---------------------------------------------------------------------------
__global__ void __launch_bounds__(256) gemm_bias_kernel(
    const float* __restrict__ A, const float* __restrict__ W,
    const float* __restrict__ bias, float* __restrict__ C)
{
    const int K = EMB;
    __shared__ float As[8][128];
    __shared__ float Ws[8][128];

    int tid = threadIdx.x;
    int m0  = blockIdx.y << 7;
    int n0  = blockIdx.x << 7;
    int lr  = tid >> 1;          // 0..127
    int lk  = (tid & 1) << 2;    // 0 or 4
    int ty  = tid >> 4;          // 0..15
    int tx  = tid & 15;          // 0..15

    float acc[8][8];
    #pragma unroll
    for (int i = 0; i < 8; i++)
        #pragma unroll
        for (int j = 0; j < 8; j++) acc[i][j] = 0.f;

    const float* Aptr = A + (size_t)(m0 + lr) * K + lk;
    const float* Wptr = W + (size_t)(n0 + lr) * K + lk;

    for (int k0 = 0; k0 < K; k0 += 8) {
        float4 a4 = *(const float4*)(Aptr + k0);
        float4 w4 = *(const float4*)(Wptr + k0);
        As[lk + 0][lr] = a4.x; As[lk + 1][lr] = a4.y;
        As[lk + 2][lr] = a4.z; As[lk + 3][lr] = a4.w;
        Ws[lk + 0][lr] = w4.x; Ws[lk + 1][lr] = w4.y;
        Ws[lk + 2][lr] = w4.z; Ws[lk + 3][lr] = w4.w;
        __syncthreads();

        #pragma unroll
        for (int kk = 0; kk < 8; kk++) {
            float4 a0 = *(const float4*)&As[kk][ty * 8];
            float4 a1 = *(const float4*)&As[kk][ty * 8 + 4];
            float4 b0 = *(const float4*)&Ws[kk][tx * 8];
            float4 b1 = *(const float4*)&Ws[kk][tx * 8 + 4];
            float ra[8] = {a0.x, a0.y, a0.z, a0.w, a1.x, a1.y, a1.z, a1.w};
            float rb[8] = {b0.x, b0.y, b0.z, b0.w, b1.x, b1.y, b1.z, b1.w};
            #pragma unroll
            for (int i = 0; i < 8; i++)
                #pragma unroll
                for (int j = 0; j < 8; j++)
                    acc[i][j] = fmaf(ra[i], rb[j], acc[i][j]);
        }
        __syncthreads();
    }

    #pragma unroll
    for (int i = 0; i < 8; i++) {
        size_t row = (size_t)(m0 + ty * 8 + i);
        #pragma unroll
        for (int j = 0; j < 8; j += 4) {
            int col = n0 + tx * 8 + j;
            float4 o;
            o.x = acc[i][j + 0] + bias[col + 0];
            o.y = acc[i][j + 1] + bias[col + 1];
            o.z = acc[i][j + 2] + bias[col + 2];
            o.w = acc[i][j + 3] + bias[col + 3];
            *(float4*)&C[row * EMB + col] = o;
        }
    }
}

// ---------------------------------------------------------------------------
// Flash-attention style kernel (fp32), 64-query x 64-key tiles, D=64.
// grid: (NSEQ/64, BATCH*NH), block: 256 (16x16, 4x4 per thread).
// Reads g_q/g_k/g_v, writes g_a (concatenated-head [4096,1024] layout).
// ---------------------------------------------------------------------------
__global__ void __launch_bounds__(256) attn_kernel()
{
    extern __shared__ float sm[];
    float* Qs   = sm;                    // 64 x 65
    float* Ks   = sm + 64 * 65;          // 64 x 65
    float* Ss   = sm + 2 * 64 * 65;      // 64 x 65
    float* Vs   = sm + 3 * 64 * 65;      // 64 x 64 (16B aligned)
    float* rowm = Vs + 64 * 64;
    float* rowl = rowm + 64;
    float* rowc = rowl + 64;

    int tid = threadIdx.x;
    int bh  = blockIdx.y;
    int b   = bh >> 4;
    int h   = bh & 15;
    int n0  = blockIdx.x << 6;
    int ty  = tid >> 4;          // 0..15
    int tx  = tid & 15;          // 0..15

    size_t rowbase = (size_t)b * NSEQ;
    int    coloff  = h * HD;

    // Load Q tile (64 rows x 64 cols), padded-row smem
    for (int p = tid; p < 64 * 16; p += 256) {
        int r = p >> 4;
        int c = (p & 15) << 2;
        float4 q4 = *(const float4*)&g_q[(rowbase + n0 + r) * EMB + coloff + c];
        Qs[r * 65 + c + 0] = q4.x; Qs[r * 65 + c + 1] = q4.y;
        Qs[r * 65 + c + 2] = q4.z; Qs[r * 65 + c + 3] = q4.w;
    }
    if (tid < 64) { rowm[tid] = -1e30f; rowl[tid] = 0.f; }

    float acc[4][4];
    #pragma unroll
    for (int i = 0; i < 4; i++)
        #pragma unroll
        for (int j = 0; j < 4; j++) acc[i][j] = 0.f;
    __syncthreads();

    for (int k0 = 0; k0 < NSEQ; k0 += 64) {
        // Load K and V tiles
        for (int p = tid; p < 64 * 16; p += 256) {
            int r = p >> 4;
            int c = (p & 15) << 2;
            size_t g = (rowbase + k0 + r) * EMB + coloff + c;
            float4 k4 = *(const float4*)&g_k[g];
            Ks[r * 65 + c + 0] = k4.x; Ks[r * 65 + c + 1] = k4.y;
            Ks[r * 65 + c + 2] = k4.z; Ks[r * 65 + c + 3] = k4.w;
            float4 v4 = *(const float4*)&g_v[g];
            *(float4*)&Vs[r * 64 + c] = v4;
        }
        __syncthreads();

        // S tile = Q K^T * scale (each thread a 4x4 sub-block)
        float s[4][4];
        #pragma unroll
        for (int i = 0; i < 4; i++)
            #pragma unroll
            for (int j = 0; j < 4; j++) s[i][j] = 0.f;

        #pragma unroll 8
        for (int d = 0; d < 64; d++) {
            float qv[4], kv[4];
            #pragma unroll
            for (int i = 0; i < 4; i++) qv[i] = Qs[(ty * 4 + i) * 65 + d];
            #pragma unroll
            for (int j = 0; j < 4; j++) kv[j] = Ks[(tx * 4 + j) * 65 + d];
            #pragma unroll
            for (int i = 0; i < 4; i++)
                #pragma unroll
                for (int j = 0; j < 4; j++)
                    s[i][j] = fmaf(qv[i], kv[j], s[i][j]);
        }
        #pragma unroll
        for (int i = 0; i < 4; i++)
            #pragma unroll
            for (int j = 0; j < 4; j++)
                Ss[(ty * 4 + i) * 65 + tx * 4 + j] = s[i][j] * SCALE;
        __syncthreads();

        // Per-row running max + correction factor
        if (tid < 64) {
            float mold = rowm[tid];
            float tmax = -1e30f;
            for (int j = 0; j < 64; j++) tmax = fmaxf(tmax, Ss[tid * 65 + j]);
            float mnew = fmaxf(mold, tmax);
            rowm[tid] = mnew;
            rowc[tid] = __expf(mold - mnew);
        }
        __syncthreads();

        // Exponentiate + rescale accumulators
        float mrow[4], crow[4];
        #pragma unroll
        for (int i = 0; i < 4; i++) {
            mrow[i] = rowm[ty * 4 + i];
            crow[i] = rowc[ty * 4 + i];
        }
        #pragma unroll
        for (int i = 0; i < 4; i++) {
            #pragma unroll
            for (int j = 0; j < 4; j++) {
                int idx = (ty * 4 + i) * 65 + tx * 4 + j;
                Ss[idx] = __expf(Ss[idx] - mrow[i]);
                acc[i][j] *= crow[i];
            }
        }
        __syncthreads();

        // Row sums (l update) — concurrent with O update (both read-only on Ss)
        if (tid < 64) {
            float sum = 0.f;
            for (int j = 0; j < 64; j++) sum += Ss[tid * 65 + j];
            rowl[tid] = rowl[tid] * rowc[tid] + sum;
        }

        // O += P @ V
        #pragma unroll 4
        for (int j = 0; j < 64; j++) {
            float pv[4];
            #pragma unroll
            for (int i = 0; i < 4; i++) pv[i] = Ss[(ty * 4 + i) * 65 + j];
            float4 v4 = *(const float4*)&Vs[j * 64 + tx * 4];
            #pragma unroll
            for (int i = 0; i < 4; i++) {
                acc[i][0] = fmaf(pv[i], v4.x, acc[i][0]);
                acc[i][1] = fmaf(pv[i], v4.y, acc[i][1]);
                acc[i][2] = fmaf(pv[i], v4.z, acc[i][2]);
                acc[i][3] = fmaf(pv[i], v4.w, acc[i][3]);
            }
        }
        __syncthreads();
    }

    // Normalize and write out (concatenated-head layout)
    #pragma unroll
    for (int i = 0; i < 4; i++) {
        float linv = 1.f / rowl[ty * 4 + i];
        size_t g = (rowbase + n0 + ty * 4 + i) * EMB + coloff + tx * 4;
        float4 o;
        o.x = acc[i][0] * linv;
        o.y = acc[i][1] * linv;
        o.z = acc[i][2] * linv;
        o.w = acc[i][3] * linv;
        *(float4*)&g_a[g] = o;
    }
}

// ---------------------------------------------------------------------------
// Launch
// ---------------------------------------------------------------------------
extern "C" void kernel_launch(void* const* d_in, const int* in_sizes, int n_in,
                              void* d_out, int out_size)
{
    const float* x  = (const float*)d_in[0];
    const float* Wq = (const float*)d_in[1];
    const float* bq = (const float*)d_in[2];
    const float* Wk = (const float*)d_in[3];
    const float* bk = (const float*)d_in[4];
    const float* Wv = (const float*)d_in[5];
    const float* bv = (const float*)d_in[6];
    const float* Wo = (const float*)d_in[7];
    const float* bo = (const float*)d_in[8];
    float* out = (float*)d_out;

    float *q, *k, *v, *a;
    cudaGetSymbolAddress((void**)&q, g_q);
    cudaGetSymbolAddress((void**)&k, g_k);
    cudaGetSymbolAddress((void**)&v, g_v);
    cudaGetSymbolAddress((void**)&a, g_a);

    const int ATTN_SMEM = (3 * 64 * 65 + 64 * 64 + 3 * 64) * (int)sizeof(float);
    cudaFuncSetAttribute(attn_kernel, cudaFuncAttributeMaxDynamicSharedMemorySize,
                         ATTN_SMEM);

    dim3 gemm_grid(EMB / 128, MROWS / 128);   // (8, 32)
    gemm_bias_kernel<<<gemm_grid, 256>>>(x, Wq, bq, q);
    gemm_bias_kernel<<<gemm_grid, 256>>>(x, Wk, bk, k);
    gemm_bias_kernel<<<gemm_grid, 256>>>(x, Wv, bv, v);

    dim3 attn_grid(NSEQ / 64, BATCH * NH);    // (32, 32)
    attn_kernel<<<attn_grid, 256, ATTN_SMEM>>>();

    gemm_bias_kernel<<<gemm_grid, 256>>>(a, Wo, bo, out);
}

// round 2
// speedup vs baseline: 2.4414x; 2.4414x over previous
#include <cuda_runtime.h>
#include <cuda_bf16.h>
#include <cstdint>

#define NSEQ   2048
#define EMB    1024
#define NH     16
#define HD     64
#define BATCH  2
#define MROWS  (BATCH * NSEQ)   // 4096
#define SCALE  0.125f           // 1/sqrt(64)

// Scratch (allocation-free rule: __device__ globals). 4 x 16MB = 64MB.
__device__ float g_q[MROWS * EMB];
__device__ float g_k[MROWS * EMB];
__device__ float g_v[MROWS * EMB];
__device__ float g_a[MROWS * EMB];

// ---------------------------------------------------------------------------
// MMA helpers
// ---------------------------------------------------------------------------
__device__ __forceinline__ void mma_bf16_k16(float* c, const uint32_t* a, const uint32_t* b)
{
    asm volatile(
        "mma.sync.aligned.m16n8k16.row.col.f32.bf16.bf16.f32 "
        "{%0,%1,%2,%3}, {%4,%5,%6,%7}, {%8,%9}, {%0,%1,%2,%3};\n"
        : "+f"(c[0]), "+f"(c[1]), "+f"(c[2]), "+f"(c[3])
        : "r"(a[0]), "r"(a[1]), "r"(a[2]), "r"(a[3]), "r"(b[0]), "r"(b[1]));
}

__device__ __forceinline__ void mma_tf32_k8(float* c, const uint32_t* a, const uint32_t* b)
{
    asm volatile(
        "mma.sync.aligned.m16n8k8.row.col.f32.tf32.tf32.f32 "
        "{%0,%1,%2,%3}, {%4,%5,%6,%7}, {%8,%9}, {%0,%1,%2,%3};\n"
        : "+f"(c[0]), "+f"(c[1]), "+f"(c[2]), "+f"(c[3])
        : "r"(a[0]), "r"(a[1]), "r"(a[2]), "r"(a[3]), "r"(b[0]), "r"(b[1]));
}

__device__ __forceinline__ uint32_t f2tf32(float x)
{
    uint32_t r;
    asm("cvt.rna.tf32.f32 %0, %1;" : "=r"(r) : "f"(x));
    return r;
}
__device__ __forceinline__ float f2tf32f(float x) { return __uint_as_float(f2tf32(x)); }

// Split two fp32 into packed bf16 hi-pair + lo-pair
__device__ __forceinline__ void split2(float v0, float v1, uint32_t& hi, uint32_t& lo)
{
    __nv_bfloat162 h = __floats2bfloat162_rn(v0, v1);       // x = v0 (low half)
    float r0 = v0 - __bfloat162float(h.x);
    float r1 = v1 - __bfloat162float(h.y);
    __nv_bfloat162 l = __floats2bfloat162_rn(r0, r1);
    hi = *reinterpret_cast<uint32_t*>(&h);
    lo = *reinterpret_cast<uint32_t*>(&l);
}

// ---------------------------------------------------------------------------
// GEMM: C[4096,1024] = A[4096,1024] @ W[1024,1024]^T + bias   (3x bf16 split)
// 128x128 tile, BK=16, 256 threads, 8 warps (4m x 2n), warp tile 32x64.
// smem word layout per row of 16 elems: words 0..7 = hi pairs, 8..15 = lo pairs,
// row stride 20 words -> conflict-free fragment loads.
// ---------------------------------------------------------------------------
__global__ void __launch_bounds__(256) gemm_bias_split_kernel(
    const float* __restrict__ A, const float* __restrict__ W,
    const float* __restrict__ bias, float* __restrict__ C)
{
    __shared__ uint32_t As[128][20];
    __shared__ uint32_t Ws[128][20];

    const int tid  = threadIdx.x;
    const int lane = tid & 31;
    const int warp = tid >> 5;
    const int g    = lane >> 2;      // 0..7
    const int tig  = lane & 3;       // 0..3
    const int warp_m = warp & 3;     // 0..3
    const int warp_n = warp >> 2;    // 0..1
    const int m0 = blockIdx.y << 7;
    const int n0 = blockIdx.x << 7;

    const int lr = tid >> 1;         // 0..127 (tile row for loads)
    const int lc = (tid & 1) << 3;   // 0 or 8 (col of 8-float chunk)
    const int wbase = lc >> 1;       // 0 or 4 (word base)

    float acc[2][8][4];
    #pragma unroll
    for (int mt = 0; mt < 2; mt++)
        #pragma unroll
        for (int nt = 0; nt < 8; nt++)
            #pragma unroll
            for (int i = 0; i < 4; i++) acc[mt][nt][i] = 0.f;

    const float* Ap = A + (size_t)(m0 + lr) * EMB + lc;
    const float* Wp = W + (size_t)(n0 + lr) * EMB + lc;

    float4 pa0 = *(const float4*)(Ap);
    float4 pa1 = *(const float4*)(Ap + 4);
    float4 pw0 = *(const float4*)(Wp);
    float4 pw1 = *(const float4*)(Wp + 4);

    // store tile 0
    {
        float va[8] = {pa0.x,pa0.y,pa0.z,pa0.w,pa1.x,pa1.y,pa1.z,pa1.w};
        float vw[8] = {pw0.x,pw0.y,pw0.z,pw0.w,pw1.x,pw1.y,pw1.z,pw1.w};
        #pragma unroll
        for (int w = 0; w < 4; w++) {
            uint32_t hi, lo;
            split2(va[2*w], va[2*w+1], hi, lo);
            As[lr][wbase + w] = hi;  As[lr][8 + wbase + w] = lo;
            split2(vw[2*w], vw[2*w+1], hi, lo);
            Ws[lr][wbase + w] = hi;  Ws[lr][8 + wbase + w] = lo;
        }
    }
    __syncthreads();

    for (int k0 = 0; k0 < EMB; k0 += 16) {
        const bool more = (k0 + 16) < EMB;
        if (more) {
            pa0 = *(const float4*)(Ap + k0 + 16);
            pa1 = *(const float4*)(Ap + k0 + 20);
            pw0 = *(const float4*)(Wp + k0 + 16);
            pw1 = *(const float4*)(Wp + k0 + 20);
        }

        // fragments
        uint32_t ah[2][4], al[2][4];
        #pragma unroll
        for (int mt = 0; mt < 2; mt++) {
            const int mr = warp_m * 32 + mt * 16;
            ah[mt][0] = As[mr + g    ][tig    ];
            ah[mt][1] = As[mr + g + 8][tig    ];
            ah[mt][2] = As[mr + g    ][tig + 4];
            ah[mt][3] = As[mr + g + 8][tig + 4];
            al[mt][0] = As[mr + g    ][8 + tig    ];
            al[mt][1] = As[mr + g + 8][8 + tig    ];
            al[mt][2] = As[mr + g    ][8 + tig + 4];
            al[mt][3] = As[mr + g + 8][8 + tig + 4];
        }
        #pragma unroll
        for (int nt = 0; nt < 8; nt++) {
            const int nr = warp_n * 64 + nt * 8 + g;
            uint32_t bh[2] = { Ws[nr][tig], Ws[nr][tig + 4] };
            uint32_t bl[2] = { Ws[nr][8 + tig], Ws[nr][8 + tig + 4] };
            #pragma unroll
            for (int mt = 0; mt < 2; mt++) {
                mma_bf16_k16(acc[mt][nt], ah[mt], bh);
                mma_bf16_k16(acc[mt][nt], ah[mt], bl);
                mma_bf16_k16(acc[mt][nt], al[mt], bh);
            }
        }
        __syncthreads();

        if (more) {
            float va[8] = {pa0.x,pa0.y,pa0.z,pa0.w,pa1.x,pa1.y,pa1.z,pa1.w};
            float vw[8] = {pw0.x,pw0.y,pw0.z,pw0.w,pw1.x,pw1.y,pw1.z,pw1.w};
            #pragma unroll
            for (int w = 0; w < 4; w++) {
                uint32_t hi, lo;
                split2(va[2*w], va[2*w+1], hi, lo);
                As[lr][wbase + w] = hi;  As[lr][8 + wbase + w] = lo;
                split2(vw[2*w], vw[2*w+1], hi, lo);
                Ws[lr][wbase + w] = hi;  Ws[lr][8 + wbase + w] = lo;
            }
            __syncthreads();
        }
    }

    // epilogue
    #pragma unroll
    for (int mt = 0; mt < 2; mt++) {
        const int r0 = m0 + warp_m * 32 + mt * 16 + g;
        #pragma unroll
        for (int nt = 0; nt < 8; nt++) {
            const int col = n0 + warp_n * 64 + nt * 8 + 2 * tig;
            const float b0 = bias[col], b1 = bias[col + 1];
            float2 o0 = { acc[mt][nt][0] + b0, acc[mt][nt][1] + b1 };
            float2 o1 = { acc[mt][nt][2] + b0, acc[mt][nt][3] + b1 };
            *(float2*)&C[(size_t)r0 * EMB + col]       = o0;
            *(float2*)&C[(size_t)(r0 + 8) * EMB + col] = o1;
        }
    }
}

// ---------------------------------------------------------------------------
// Flash attention, tf32 mma. Block = 128 threads (4 warps x 16 query rows),
// 64 queries per block, key tiles of 64. grid (NSEQ/64, BATCH*NH).
// ---------------------------------------------------------------------------
#define SSS 68   // Ss/Ks row stride (floats)
#define SVS 72   // Vs row stride (floats)

__global__ void __launch_bounds__(128) attn_mma_kernel()
{
    extern __shared__ float sm[];
    float* Ks   = sm;                       // 64 x 68
    float* Vs   = Ks + 64 * SSS;            // 64 x 72
    float* Ss   = Vs + 64 * SVS;            // 64 x 68  (also Q staging)
    float* rowm = Ss + 64 * SSS;
    float* rowl = rowm + 64;
    float* rowc = rowl + 64;

    const int tid  = threadIdx.x;
    const int lane = tid & 31;
    const int warp = tid >> 5;
    const int g    = lane >> 2;
    const int tig  = lane & 3;
    const int qrow = warp * 16;

    const int bh = blockIdx.y;
    const int b  = bh >> 4;
    const int h  = bh & 15;
    const int n0 = blockIdx.x << 6;
    const size_t rowbase = (size_t)b * NSEQ;
    const int    coloff  = h * HD;

    // stage Q into Ss (tf32-rounded)
    for (int p = tid; p < 64 * 16; p += 128) {
        const int r = p >> 4;
        const int c = (p & 15) << 2;
        float4 q4 = *(const float4*)&g_q[(rowbase + n0 + r) * EMB + coloff + c];
        Ss[r * SSS + c + 0] = f2tf32f(q4.x);
        Ss[r * SSS + c + 1] = f2tf32f(q4.y);
        Ss[r * SSS + c + 2] = f2tf32f(q4.z);
        Ss[r * SSS + c + 3] = f2tf32f(q4.w);
    }
    if (tid < 64) { rowm[tid] = -1e30f; rowl[tid] = 0.f; }
    __syncthreads();

    // Q fragments (kept in registers across the whole key loop)
    uint32_t qf[8][4];
    #pragma unroll
    for (int ks = 0; ks < 8; ks++) {
        qf[ks][0] = __float_as_uint(Ss[(qrow + g    ) * SSS + ks * 8 + tig    ]);
        qf[ks][1] = __float_as_uint(Ss[(qrow + g + 8) * SSS + ks * 8 + tig    ]);
        qf[ks][2] = __float_as_uint(Ss[(qrow + g    ) * SSS + ks * 8 + tig + 4]);
        qf[ks][3] = __float_as_uint(Ss[(qrow + g + 8) * SSS + ks * 8 + tig + 4]);
    }
    __syncthreads();

    float of[8][4];
    #pragma unroll
    for (int nt = 0; nt < 8; nt++)
        #pragma unroll
        for (int i = 0; i < 4; i++) of[nt][i] = 0.f;

    for (int k0 = 0; k0 < NSEQ; k0 += 64) {
        // load K/V tile (tf32-rounded)
        for (int p = tid; p < 64 * 16; p += 128) {
            const int r = p >> 4;
            const int c = (p & 15) << 2;
            const size_t gidx = (rowbase + k0 + r) * EMB + coloff + c;
            float4 k4 = *(const float4*)&g_k[gidx];
            Ks[r * SSS + c + 0] = f2tf32f(k4.x);
            Ks[r * SSS + c + 1] = f2tf32f(k4.y);
            Ks[r * SSS + c + 2] = f2tf32f(k4.z);
            Ks[r * SSS + c + 3] = f2tf32f(k4.w);
            float4 v4 = *(const float4*)&g_v[gidx];
            Vs[r * SVS + c + 0] = f2tf32f(v4.x);
            Vs[r * SVS + c + 1] = f2tf32f(v4.y);
            Vs[r * SVS + c + 2] = f2tf32f(v4.z);
            Vs[r * SVS + c + 3] = f2tf32f(v4.w);
        }
        __syncthreads();

        // S = Q K^T
        float sf[8][4];
        #pragma unroll
        for (int nt = 0; nt < 8; nt++)
            #pragma unroll
            for (int i = 0; i < 4; i++) sf[nt][i] = 0.f;

        #pragma unroll
        for (int ks = 0; ks < 8; ks++) {
            #pragma unroll
            for (int nt = 0; nt < 8; nt++) {
                uint32_t bf[2] = {
                    __float_as_uint(Ks[(nt * 8 + g) * SSS + ks * 8 + tig    ]),
                    __float_as_uint(Ks[(nt * 8 + g) * SSS + ks * 8 + tig + 4]) };
                mma_tf32_k8(sf[nt], qf[ks], bf);
            }
        }
        // store scaled S
        #pragma unroll
        for (int nt = 0; nt < 8; nt++) {
            const int c = nt * 8 + 2 * tig;
            Ss[(qrow + g    ) * SSS + c    ] = sf[nt][0] * SCALE;
            Ss[(qrow + g    ) * SSS + c + 1] = sf[nt][1] * SCALE;
            Ss[(qrow + g + 8) * SSS + c    ] = sf[nt][2] * SCALE;
            Ss[(qrow + g + 8) * SSS + c + 1] = sf[nt][3] * SCALE;
        }
        __syncthreads();

        // row max + correction
        if (tid < 64) {
            const float mold = rowm[tid];
            float tmax = -1e30f;
            for (int j = 0; j < 64; j++) tmax = fmaxf(tmax, Ss[tid * SSS + j]);
            const float mnew = fmaxf(mold, tmax);
            rowm[tid] = mnew;
            rowc[tid] = __expf(mold - mnew);
        }
        __syncthreads();

        // exp (tf32-rounded so PV fragments are consistent)
        {
            const int r  = tid & 63;
            const int c0 = (tid >> 6) * 32;
            const float m = rowm[r];
            #pragma unroll 8
            for (int c = 0; c < 32; c++) {
                const int idx = r * SSS + c0 + c;
                Ss[idx] = f2tf32f(__expf(Ss[idx] - m));
            }
        }
        __syncthreads();

        // row sums
        if (tid < 64) {
            float s = 0.f;
            for (int j = 0; j < 64; j++) s += Ss[tid * SSS + j];
            rowl[tid] = rowl[tid] * rowc[tid] + s;
        }

        // rescale O
        const float cr0 = rowc[qrow + g];
        const float cr1 = rowc[qrow + g + 8];
        #pragma unroll
        for (int nt = 0; nt < 8; nt++) {
            of[nt][0] *= cr0; of[nt][1] *= cr0;
            of[nt][2] *= cr1; of[nt][3] *= cr1;
        }

        // O += P V
        #pragma unroll
        for (int ks = 0; ks < 8; ks++) {
            uint32_t pf[4] = {
                __float_as_uint(Ss[(qrow + g    ) * SSS + ks * 8 + tig    ]),
                __float_as_uint(Ss[(qrow + g + 8) * SSS + ks * 8 + tig    ]),
                __float_as_uint(Ss[(qrow + g    ) * SSS + ks * 8 + tig + 4]),
                __float_as_uint(Ss[(qrow + g + 8) * SSS + ks * 8 + tig + 4]) };
            #pragma unroll
            for (int nt = 0; nt < 8; nt++) {
                uint32_t bv[2] = {
                    __float_as_uint(Vs[(ks * 8 + tig    ) * SVS + nt * 8 + g]),
                    __float_as_uint(Vs[(ks * 8 + tig + 4) * SVS + nt * 8 + g]) };
                mma_tf32_k8(of[nt], pf, bv);
            }
        }
        __syncthreads();
    }

    // epilogue: normalize, write
    const float li0 = 1.f / rowl[qrow + g];
    const float li1 = 1.f / rowl[qrow + g + 8];
    const size_t r0 = (rowbase + n0 + qrow + g) * EMB;
    const size_t r1 = r0 + 8 * EMB;
    #pragma unroll
    for (int nt = 0; nt < 8; nt++) {
        const int col = coloff + nt * 8 + 2 * tig;
        float2 o0 = { of[nt][0] * li0, of[nt][1] * li0 };
        float2 o1 = { of[nt][2] * li1, of[nt][3] * li1 };
        *(float2*)&g_a[r0 + col] = o0;
        *(float2*)&g_a[r1 + col] = o1;
    }
}

// ---------------------------------------------------------------------------
// Launch
// ---------------------------------------------------------------------------
extern "C" void kernel_launch(void* const* d_in, const int* in_sizes, int n_in,
                              void* d_out, int out_size)
{
    const float* x  = (const float*)d_in[0];
    const float* Wq = (const float*)d_in[1];
    const float* bq = (const float*)d_in[2];
    const float* Wk = (const float*)d_in[3];
    const float* bk = (const float*)d_in[4];
    const float* Wv = (const float*)d_in[5];
    const float* bv = (const float*)d_in[6];
    const float* Wo = (const float*)d_in[7];
    const float* bo = (const float*)d_in[8];
    float* out = (float*)d_out;

    float *q, *k, *v, *a;
    cudaGetSymbolAddress((void**)&q, g_q);
    cudaGetSymbolAddress((void**)&k, g_k);
    cudaGetSymbolAddress((void**)&v, g_v);
    cudaGetSymbolAddress((void**)&a, g_a);

    const int ATTN_SMEM = (64 * SSS + 64 * SVS + 64 * SSS + 3 * 64) * (int)sizeof(float);
    static bool attr_set = false;
    cudaFuncSetAttribute(attn_mma_kernel, cudaFuncAttributeMaxDynamicSharedMemorySize,
                         ATTN_SMEM);
    (void)attr_set;

    dim3 gemm_grid(EMB / 128, MROWS / 128);   // (8, 32)
    gemm_bias_split_kernel<<<gemm_grid, 256>>>(x, Wq, bq, q);
    gemm_bias_split_kernel<<<gemm_grid, 256>>>(x, Wk, bk, k);
    gemm_bias_split_kernel<<<gemm_grid, 256>>>(x, Wv, bv, v);

    dim3 attn_grid(NSEQ / 64, BATCH * NH);    // (32, 32)
    attn_mma_kernel<<<attn_grid, 128, ATTN_SMEM>>>();

    gemm_bias_split_kernel<<<gemm_grid, 256>>>(a, Wo, bo, out);
}

// round 3
// speedup vs baseline: 2.5159x; 1.0305x over previous
#include <cuda_runtime.h>
#include <cuda_bf16.h>
#include <cstdint>

#define NSEQ   2048
#define EMB    1024
#define NH     16
#define HD     64
#define BATCH  2
#define MROWS  (BATCH * NSEQ)   // 4096
#define SCALE  0.125f           // 1/sqrt(64)

// Scratch (allocation-free rule: __device__ globals). 4 x 16MB = 64MB.
__device__ float g_q[MROWS * EMB];
__device__ float g_k[MROWS * EMB];
__device__ float g_v[MROWS * EMB];
__device__ float g_a[MROWS * EMB];

// ---------------------------------------------------------------------------
// MMA helpers
// ---------------------------------------------------------------------------
__device__ __forceinline__ void mma_bf16_k16(float* c, const uint32_t* a, const uint32_t* b)
{
    asm volatile(
        "mma.sync.aligned.m16n8k16.row.col.f32.bf16.bf16.f32 "
        "{%0,%1,%2,%3}, {%4,%5,%6,%7}, {%8,%9}, {%0,%1,%2,%3};\n"
        : "+f"(c[0]), "+f"(c[1]), "+f"(c[2]), "+f"(c[3])
        : "r"(a[0]), "r"(a[1]), "r"(a[2]), "r"(a[3]), "r"(b[0]), "r"(b[1]));
}

__device__ __forceinline__ void mma_tf32_k8(float* c, const uint32_t* a, const uint32_t* b)
{
    asm volatile(
        "mma.sync.aligned.m16n8k8.row.col.f32.tf32.tf32.f32 "
        "{%0,%1,%2,%3}, {%4,%5,%6,%7}, {%8,%9}, {%0,%1,%2,%3};\n"
        : "+f"(c[0]), "+f"(c[1]), "+f"(c[2]), "+f"(c[3])
        : "r"(a[0]), "r"(a[1]), "r"(a[2]), "r"(a[3]), "r"(b[0]), "r"(b[1]));
}

__device__ __forceinline__ uint32_t packbf(float lo, float hi)
{
    __nv_bfloat162 h = __floats2bfloat162_rn(lo, hi);   // .x = lo half
    return *reinterpret_cast<uint32_t*>(&h);
}

// Split two fp32 into packed bf16 hi-pair + lo-pair
__device__ __forceinline__ void split2(float v0, float v1, uint32_t& hi, uint32_t& lo)
{
    __nv_bfloat162 h = __floats2bfloat162_rn(v0, v1);
    float r0 = v0 - __bfloat162float(h.x);
    float r1 = v1 - __bfloat162float(h.y);
    __nv_bfloat162 l = __floats2bfloat162_rn(r0, r1);
    hi = *reinterpret_cast<uint32_t*>(&h);
    lo = *reinterpret_cast<uint32_t*>(&l);
}

__device__ __forceinline__ uint32_t smem_u32(const void* p)
{
    return (uint32_t)__cvta_generic_to_shared(p);
}

// ---------------------------------------------------------------------------
// GEMM: C[4096,1024] = A[4096,1024] @ W[1024,1024]^T + bias   (3x bf16 split)
// 128x128 tile, BK=16, 256 threads, 8 warps (4m x 2n), double-buffered smem.
// ---------------------------------------------------------------------------
__global__ void __launch_bounds__(256) gemm_bias_split_kernel(
    const float* __restrict__ A, const float* __restrict__ W,
    const float* __restrict__ bias, float* __restrict__ C)
{
    __shared__ uint32_t As[2][128][20];
    __shared__ uint32_t Ws[2][128][20];

    const int tid  = threadIdx.x;
    const int lane = tid & 31;
    const int warp = tid >> 5;
    const int g    = lane >> 2;      // 0..7
    const int tig  = lane & 3;       // 0..3
    const int warp_m = warp & 3;     // 0..3
    const int warp_n = warp >> 2;    // 0..1
    const int m0 = blockIdx.y << 7;
    const int n0 = blockIdx.x << 7;

    const int lr = tid >> 1;         // 0..127
    const int lc = (tid & 1) << 3;   // 0 or 8
    const int wbase = lc >> 1;       // 0 or 4

    float acc[2][8][4];
    #pragma unroll
    for (int mt = 0; mt < 2; mt++)
        #pragma unroll
        for (int nt = 0; nt < 8; nt++)
            #pragma unroll
            for (int i = 0; i < 4; i++) acc[mt][nt][i] = 0.f;

    const float* Ap = A + (size_t)(m0 + lr) * EMB + lc;
    const float* Wp = W + (size_t)(n0 + lr) * EMB + lc;

    float4 pa0 = *(const float4*)(Ap);
    float4 pa1 = *(const float4*)(Ap + 4);
    float4 pw0 = *(const float4*)(Wp);
    float4 pw1 = *(const float4*)(Wp + 4);

    // store tile 0 into buffer 0
    {
        float va[8] = {pa0.x,pa0.y,pa0.z,pa0.w,pa1.x,pa1.y,pa1.z,pa1.w};
        float vw[8] = {pw0.x,pw0.y,pw0.z,pw0.w,pw1.x,pw1.y,pw1.z,pw1.w};
        #pragma unroll
        for (int w = 0; w < 4; w++) {
            uint32_t hi, lo;
            split2(va[2*w], va[2*w+1], hi, lo);
            As[0][lr][wbase + w] = hi;  As[0][lr][8 + wbase + w] = lo;
            split2(vw[2*w], vw[2*w+1], hi, lo);
            Ws[0][lr][wbase + w] = hi;  Ws[0][lr][8 + wbase + w] = lo;
        }
    }
    __syncthreads();

    int bsel = 0;
    for (int k0 = 0; k0 < EMB; k0 += 16) {
        const bool more = (k0 + 16) < EMB;
        if (more) {
            pa0 = *(const float4*)(Ap + k0 + 16);
            pa1 = *(const float4*)(Ap + k0 + 20);
            pw0 = *(const float4*)(Wp + k0 + 16);
            pw1 = *(const float4*)(Wp + k0 + 20);
        }

        // fragments + mma from buffer bsel
        uint32_t ah[2][4], al[2][4];
        #pragma unroll
        for (int mt = 0; mt < 2; mt++) {
            const int mr = warp_m * 32 + mt * 16;
            ah[mt][0] = As[bsel][mr + g    ][tig    ];
            ah[mt][1] = As[bsel][mr + g + 8][tig    ];
            ah[mt][2] = As[bsel][mr + g    ][tig + 4];
            ah[mt][3] = As[bsel][mr + g + 8][tig + 4];
            al[mt][0] = As[bsel][mr + g    ][8 + tig    ];
            al[mt][1] = As[bsel][mr + g + 8][8 + tig    ];
            al[mt][2] = As[bsel][mr + g    ][8 + tig + 4];
            al[mt][3] = As[bsel][mr + g + 8][8 + tig + 4];
        }
        #pragma unroll
        for (int nt = 0; nt < 8; nt++) {
            const int nr = warp_n * 64 + nt * 8 + g;
            uint32_t bh[2] = { Ws[bsel][nr][tig], Ws[bsel][nr][tig + 4] };
            uint32_t bl[2] = { Ws[bsel][nr][8 + tig], Ws[bsel][nr][8 + tig + 4] };
            #pragma unroll
            for (int mt = 0; mt < 2; mt++) {
                mma_bf16_k16(acc[mt][nt], ah[mt], bh);
                mma_bf16_k16(acc[mt][nt], ah[mt], bl);
                mma_bf16_k16(acc[mt][nt], al[mt], bh);
            }
        }

        if (more) {
            const int nb = bsel ^ 1;
            float va[8] = {pa0.x,pa0.y,pa0.z,pa0.w,pa1.x,pa1.y,pa1.z,pa1.w};
            float vw[8] = {pw0.x,pw0.y,pw0.z,pw0.w,pw1.x,pw1.y,pw1.z,pw1.w};
            #pragma unroll
            for (int w = 0; w < 4; w++) {
                uint32_t hi, lo;
                split2(va[2*w], va[2*w+1], hi, lo);
                As[nb][lr][wbase + w] = hi;  As[nb][lr][8 + wbase + w] = lo;
                split2(vw[2*w], vw[2*w+1], hi, lo);
                Ws[nb][lr][wbase + w] = hi;  Ws[nb][lr][8 + wbase + w] = lo;
            }
            __syncthreads();
            bsel = nb;
        }
    }

    // epilogue
    #pragma unroll
    for (int mt = 0; mt < 2; mt++) {
        const int r0 = m0 + warp_m * 32 + mt * 16 + g;
        #pragma unroll
        for (int nt = 0; nt < 8; nt++) {
            const int col = n0 + warp_n * 64 + nt * 8 + 2 * tig;
            const float b0 = bias[col], b1 = bias[col + 1];
            float2 o0 = { acc[mt][nt][0] + b0, acc[mt][nt][1] + b1 };
            float2 o1 = { acc[mt][nt][2] + b0, acc[mt][nt][3] + b1 };
            *(float2*)&C[(size_t)r0 * EMB + col]       = o0;
            *(float2*)&C[(size_t)(r0 + 8) * EMB + col] = o1;
        }
    }
}

// ---------------------------------------------------------------------------
// Flash attention, register-resident softmax.
// Block = 128 threads (4 warps), 64 q rows per block, key tiles of 64.
// QK^T: tf32 mma (K tf32 in smem via cp.async, double-buffered).
// softmax: in registers (shuffle reductions over 4-lane groups).
// PV: bf16 mma, P packed in registers, V packed bf16 key-pairs in smem.
// ---------------------------------------------------------------------------
#define KST 68   // K smem row stride (floats)
#define VST 36   // Vt smem row stride (u32 key-pairs)
#define KBUF (64 * KST)
#define VBUF (64 * VST)

__global__ void __launch_bounds__(128) attn_mma_kernel()
{
    extern __shared__ char smraw[];
    float*    Ks = (float*)smraw;                  // [2][64*KST]
    uint32_t* Vt = (uint32_t*)(Ks + 2 * KBUF);     // [2][64*VST]

    const int tid  = threadIdx.x;
    const int lane = tid & 31;
    const int warp = tid >> 5;
    const int g    = lane >> 2;      // 0..7
    const int tig  = lane & 3;       // 0..3
    const int qrow = warp * 16;

    const int bh = blockIdx.y;
    const int b  = bh >> 4;
    const int h  = bh & 15;
    const int n0 = blockIdx.x << 6;
    const size_t rowbase = (size_t)b * NSEQ;
    const int    coloff  = h * HD;

    const float* Kbase = g_k + rowbase * EMB + coloff;
    const float* Vbase = g_v + rowbase * EMB + coloff;

    // ---- stage Q (pre-scaled) into Ks[0], pull fragments to registers ----
    for (int p = tid; p < 1024; p += 128) {
        const int r  = p >> 4;
        const int c4 = (p & 15) << 2;
        float4 q4 = *(const float4*)&g_q[(rowbase + n0 + r) * EMB + coloff + c4];
        Ks[r * KST + c4 + 0] = q4.x * SCALE;
        Ks[r * KST + c4 + 1] = q4.y * SCALE;
        Ks[r * KST + c4 + 2] = q4.z * SCALE;
        Ks[r * KST + c4 + 3] = q4.w * SCALE;
    }
    __syncthreads();

    uint32_t qf[8][4];
    #pragma unroll
    for (int ks = 0; ks < 8; ks++) {
        qf[ks][0] = __float_as_uint(Ks[(qrow + g    ) * KST + ks * 8 + tig    ]);
        qf[ks][1] = __float_as_uint(Ks[(qrow + g + 8) * KST + ks * 8 + tig    ]);
        qf[ks][2] = __float_as_uint(Ks[(qrow + g    ) * KST + ks * 8 + tig + 4]);
        qf[ks][3] = __float_as_uint(Ks[(qrow + g + 8) * KST + ks * 8 + tig + 4]);
    }
    __syncthreads();

    float of[8][4];
    #pragma unroll
    for (int dt = 0; dt < 8; dt++)
        #pragma unroll
        for (int i = 0; i < 4; i++) of[dt][i] = 0.f;

    float m0 = -1e30f, m1 = -1e30f, l0 = 0.f, l1 = 0.f;

    const int vp  = lane;                 // key-pair index 0..31
    const int vcg = warp << 2;            // col group base (4 groups of 4 cols)

    // V prefetch registers (tile t+1 loaded during tile t compute)
    float4 vreg[8];

    // ---- prologue: start loads for tile 0 ----
    {
        const float* p0 = Vbase + (size_t)(2 * vp) * EMB;
        #pragma unroll
        for (int i = 0; i < 4; i++) {
            const int cg = vcg + i;
            vreg[2*i]   = *(const float4*)(p0 + cg * 4);
            vreg[2*i+1] = *(const float4*)(p0 + EMB + cg * 4);
        }
        #pragma unroll
        for (int i = 0; i < 8; i++) {
            const int idx = tid + i * 128;
            const int r = idx >> 4, c4 = (idx & 15) << 2;
            asm volatile("cp.async.cg.shared.global [%0], [%1], 16;\n" ::
                "r"(smem_u32(Ks + r * KST + c4)),
                "l"(Kbase + (size_t)r * EMB + c4));
        }
        asm volatile("cp.async.commit_group;\n");
    }

    for (int t = 0; t < NSEQ / 64; t++) {
        const int buf = t & 1;
        float*    kbuf = Ks + buf * KBUF;
        uint32_t* vbuf = Vt + buf * VBUF;

        // pack prefetched V into smem (bf16 key-pairs, transposed)
        #pragma unroll
        for (int i = 0; i < 4; i++) {
            const int cg = vcg + i;
            float4 a = vreg[2*i], c = vreg[2*i+1];
            vbuf[(cg * 4 + 0) * VST + vp] = packbf(a.x, c.x);
            vbuf[(cg * 4 + 1) * VST + vp] = packbf(a.y, c.y);
            vbuf[(cg * 4 + 2) * VST + vp] = packbf(a.z, c.z);
            vbuf[(cg * 4 + 3) * VST + vp] = packbf(a.w, c.w);
        }
        asm volatile("cp.async.wait_group 0;\n" ::: "memory");
        __syncthreads();

        // issue loads for next tile
        if (t + 1 < NSEQ / 64) {
            const int k0n = (t + 1) * 64;
            const float* p0 = Vbase + (size_t)(k0n + 2 * vp) * EMB;
            #pragma unroll
            for (int i = 0; i < 4; i++) {
                const int cg = vcg + i;
                vreg[2*i]   = *(const float4*)(p0 + cg * 4);
                vreg[2*i+1] = *(const float4*)(p0 + EMB + cg * 4);
            }
            float* knext = Ks + (buf ^ 1) * KBUF;
            #pragma unroll
            for (int i = 0; i < 8; i++) {
                const int idx = tid + i * 128;
                const int r = idx >> 4, c4 = (idx & 15) << 2;
                asm volatile("cp.async.cg.shared.global [%0], [%1], 16;\n" ::
                    "r"(smem_u32(knext + r * KST + c4)),
                    "l"(Kbase + (size_t)(k0n + r) * EMB + c4));
            }
            asm volatile("cp.async.commit_group;\n");
        }

        // ---- S = Q K^T (tf32) ----
        float sf[8][4];
        #pragma unroll
        for (int nt = 0; nt < 8; nt++)
            #pragma unroll
            for (int i = 0; i < 4; i++) sf[nt][i] = 0.f;

        #pragma unroll
        for (int ks = 0; ks < 8; ks++) {
            #pragma unroll
            for (int nt = 0; nt < 8; nt++) {
                uint32_t bf[2] = {
                    __float_as_uint(kbuf[(nt * 8 + g) * KST + ks * 8 + tig    ]),
                    __float_as_uint(kbuf[(nt * 8 + g) * KST + ks * 8 + tig + 4]) };
                mma_tf32_k8(sf[nt], qf[ks], bf);
            }
        }

        // ---- register softmax ----
        float mt0 = -1e30f, mt1 = -1e30f;
        #pragma unroll
        for (int nt = 0; nt < 8; nt++) {
            mt0 = fmaxf(mt0, fmaxf(sf[nt][0], sf[nt][1]));
            mt1 = fmaxf(mt1, fmaxf(sf[nt][2], sf[nt][3]));
        }
        mt0 = fmaxf(mt0, __shfl_xor_sync(0xffffffffu, mt0, 1));
        mt0 = fmaxf(mt0, __shfl_xor_sync(0xffffffffu, mt0, 2));
        mt1 = fmaxf(mt1, __shfl_xor_sync(0xffffffffu, mt1, 1));
        mt1 = fmaxf(mt1, __shfl_xor_sync(0xffffffffu, mt1, 2));

        const float mn0 = fmaxf(m0, mt0);
        const float mn1 = fmaxf(m1, mt1);
        const float c0 = __expf(m0 - mn0);
        const float c1 = __expf(m1 - mn1);
        m0 = mn0; m1 = mn1;

        float s0 = 0.f, s1 = 0.f;
        uint32_t pf[4][4];
        #pragma unroll
        for (int kc = 0; kc < 4; kc++) {
            #pragma unroll
            for (int hh = 0; hh < 2; hh++) {
                const int nt = 2 * kc + hh;
                float p0 = __expf(sf[nt][0] - mn0);
                float p1 = __expf(sf[nt][1] - mn0);
                float p2 = __expf(sf[nt][2] - mn1);
                float p3 = __expf(sf[nt][3] - mn1);
                s0 += p0 + p1;
                s1 += p2 + p3;
                pf[kc][2 * hh    ] = packbf(p0, p1);   // row g
                pf[kc][2 * hh + 1] = packbf(p2, p3);   // row g+8
            }
        }
        s0 += __shfl_xor_sync(0xffffffffu, s0, 1);
        s0 += __shfl_xor_sync(0xffffffffu, s0, 2);
        s1 += __shfl_xor_sync(0xffffffffu, s1, 1);
        s1 += __shfl_xor_sync(0xffffffffu, s1, 2);
        l0 = l0 * c0 + s0;
        l1 = l1 * c1 + s1;

        #pragma unroll
        for (int dt = 0; dt < 8; dt++) {
            of[dt][0] *= c0; of[dt][1] *= c0;
            of[dt][2] *= c1; of[dt][3] *= c1;
        }

        // ---- O += P V (bf16) ----
        #pragma unroll
        for (int kc = 0; kc < 4; kc++) {
            #pragma unroll
            for (int dt = 0; dt < 8; dt++) {
                const uint32_t* vrow = vbuf + (dt * 8 + g) * VST + kc * 8;
                uint32_t bv[2] = { vrow[tig], vrow[4 + tig] };
                mma_bf16_k16(of[dt], pf[kc], bv);
            }
        }
        // no end-of-iter sync needed: next iteration's sync (after wait_group)
        // orders buffer reuse across warps.
    }

    // ---- epilogue: normalize, write ----
    const float li0 = 1.f / l0;
    const float li1 = 1.f / l1;
    const size_t r0 = (rowbase + n0 + qrow + g) * EMB + coloff;
    const size_t r1 = r0 + (size_t)8 * EMB;
    #pragma unroll
    for (int dt = 0; dt < 8; dt++) {
        const int col = dt * 8 + 2 * tig;
        float2 o0 = { of[dt][0] * li0, of[dt][1] * li0 };
        float2 o1 = { of[dt][2] * li1, of[dt][3] * li1 };
        *(float2*)&g_a[r0 + col] = o0;
        *(float2*)&g_a[r1 + col] = o1;
    }
}

// ---------------------------------------------------------------------------
// Launch
// ---------------------------------------------------------------------------
extern "C" void kernel_launch(void* const* d_in, const int* in_sizes, int n_in,
                              void* d_out, int out_size)
{
    const float* x  = (const float*)d_in[0];
    const float* Wq = (const float*)d_in[1];
    const float* bq = (const float*)d_in[2];
    const float* Wk = (const float*)d_in[3];
    const float* bk = (const float*)d_in[4];
    const float* Wv = (const float*)d_in[5];
    const float* bv = (const float*)d_in[6];
    const float* Wo = (const float*)d_in[7];
    const float* bo = (const float*)d_in[8];
    float* out = (float*)d_out;

    float *q, *k, *v, *a;
    cudaGetSymbolAddress((void**)&q, g_q);
    cudaGetSymbolAddress((void**)&k, g_k);
    cudaGetSymbolAddress((void**)&v, g_v);
    cudaGetSymbolAddress((void**)&a, g_a);

    const int ATTN_SMEM = (2 * KBUF + 2 * VBUF) * (int)sizeof(float);
    cudaFuncSetAttribute(attn_mma_kernel, cudaFuncAttributeMaxDynamicSharedMemorySize,
                         ATTN_SMEM);

    dim3 gemm_grid(EMB / 128, MROWS / 128);   // (8, 32)
    gemm_bias_split_kernel<<<gemm_grid, 256>>>(x, Wq, bq, q);
    gemm_bias_split_kernel<<<gemm_grid, 256>>>(x, Wk, bk, k);
    gemm_bias_split_kernel<<<gemm_grid, 256>>>(x, Wv, bv, v);

    dim3 attn_grid(NSEQ / 64, BATCH * NH);    // (32, 32)
    attn_mma_kernel<<<attn_grid, 128, ATTN_SMEM>>>();

    gemm_bias_split_kernel<<<gemm_grid, 256>>>(a, Wo, bo, out);
}

// round 4
// speedup vs baseline: 3.3478x; 1.3306x over previous
#include <cuda_runtime.h>
#include <cuda_bf16.h>
#include <cuda_fp16.h>
#include <cstdint>

#define NSEQ   2048
#define EMB    1024
#define NH     16
#define HD     64
#define BATCH  2
#define MROWS  (BATCH * NSEQ)   // 4096
#define SCALE  0.125f           // 1/sqrt(64)

// Scratch (allocation-free rule: __device__ globals).
__device__ __half g_qh[MROWS * EMB];   // 8MB
__device__ __half g_kh[MROWS * EMB];   // 8MB
__device__ __half g_vh[MROWS * EMB];   // 8MB
__device__ float  g_a [MROWS * EMB];   // 16MB

// ---------------------------------------------------------------------------
// MMA / ldmatrix helpers
// ---------------------------------------------------------------------------
__device__ __forceinline__ void mma_bf16_k16(float* c, const uint32_t* a, const uint32_t* b)
{
    asm volatile(
        "mma.sync.aligned.m16n8k16.row.col.f32.bf16.bf16.f32 "
        "{%0,%1,%2,%3}, {%4,%5,%6,%7}, {%8,%9}, {%0,%1,%2,%3};\n"
        : "+f"(c[0]), "+f"(c[1]), "+f"(c[2]), "+f"(c[3])
        : "r"(a[0]), "r"(a[1]), "r"(a[2]), "r"(a[3]), "r"(b[0]), "r"(b[1]));
}

__device__ __forceinline__ void mma_f16_k16(float* c, const uint32_t* a, const uint32_t* b)
{
    asm volatile(
        "mma.sync.aligned.m16n8k16.row.col.f32.f16.f16.f32 "
        "{%0,%1,%2,%3}, {%4,%5,%6,%7}, {%8,%9}, {%0,%1,%2,%3};\n"
        : "+f"(c[0]), "+f"(c[1]), "+f"(c[2]), "+f"(c[3])
        : "r"(a[0]), "r"(a[1]), "r"(a[2]), "r"(a[3]), "r"(b[0]), "r"(b[1]));
}

__device__ __forceinline__ void ldsm_x4(uint32_t* r, uint32_t addr)
{
    asm volatile("ldmatrix.sync.aligned.m8n8.x4.shared.b16 {%0,%1,%2,%3}, [%4];"
        : "=r"(r[0]), "=r"(r[1]), "=r"(r[2]), "=r"(r[3]) : "r"(addr));
}

__device__ __forceinline__ void ldsm_x4_t(uint32_t* r, uint32_t addr)
{
    asm volatile("ldmatrix.sync.aligned.m8n8.x4.trans.shared.b16 {%0,%1,%2,%3}, [%4];"
        : "=r"(r[0]), "=r"(r[1]), "=r"(r[2]), "=r"(r[3]) : "r"(addr));
}

__device__ __forceinline__ uint32_t packh(float lo, float hi)
{
    __half2 h = __floats2half2_rn(lo, hi);
    return *reinterpret_cast<uint32_t*>(&h);
}

// Split two fp32 into packed bf16 hi-pair + lo-pair
__device__ __forceinline__ void split2(float v0, float v1, uint32_t& hi, uint32_t& lo)
{
    __nv_bfloat162 h = __floats2bfloat162_rn(v0, v1);
    float r0 = v0 - __bfloat162float(h.x);
    float r1 = v1 - __bfloat162float(h.y);
    __nv_bfloat162 l = __floats2bfloat162_rn(r0, r1);
    hi = *reinterpret_cast<uint32_t*>(&h);
    lo = *reinterpret_cast<uint32_t*>(&l);
}

__device__ __forceinline__ uint32_t smem_u32(const void* p)
{
    return (uint32_t)__cvta_generic_to_shared(p);
}

// ---------------------------------------------------------------------------
// GEMM: C[4096,1024] = A[4096,1024] @ W[1024,1024]^T + bias   (3x bf16 split)
// 128x128 tile, BK=16, 256 threads, 8 warps (4m x 2n), double-buffered smem.
// OutT = float (fp32 store) or __half (fp16 store).
// ---------------------------------------------------------------------------
template <typename OutT>
__global__ void __launch_bounds__(256) gemm_bias_split_kernel(
    const float* __restrict__ A, const float* __restrict__ W,
    const float* __restrict__ bias, OutT* __restrict__ C)
{
    __shared__ uint32_t As[2][128][20];
    __shared__ uint32_t Ws[2][128][20];

    const int tid  = threadIdx.x;
    const int lane = tid & 31;
    const int warp = tid >> 5;
    const int g    = lane >> 2;
    const int tig  = lane & 3;
    const int warp_m = warp & 3;
    const int warp_n = warp >> 2;
    const int m0 = blockIdx.y << 7;
    const int n0 = blockIdx.x << 7;

    const int lr = tid >> 1;
    const int lc = (tid & 1) << 3;
    const int wbase = lc >> 1;

    float acc[2][8][4];
    #pragma unroll
    for (int mt = 0; mt < 2; mt++)
        #pragma unroll
        for (int nt = 0; nt < 8; nt++)
            #pragma unroll
            for (int i = 0; i < 4; i++) acc[mt][nt][i] = 0.f;

    const float* Ap = A + (size_t)(m0 + lr) * EMB + lc;
    const float* Wp = W + (size_t)(n0 + lr) * EMB + lc;

    float4 pa0 = *(const float4*)(Ap);
    float4 pa1 = *(const float4*)(Ap + 4);
    float4 pw0 = *(const float4*)(Wp);
    float4 pw1 = *(const float4*)(Wp + 4);

    {
        float va[8] = {pa0.x,pa0.y,pa0.z,pa0.w,pa1.x,pa1.y,pa1.z,pa1.w};
        float vw[8] = {pw0.x,pw0.y,pw0.z,pw0.w,pw1.x,pw1.y,pw1.z,pw1.w};
        #pragma unroll
        for (int w = 0; w < 4; w++) {
            uint32_t hi, lo;
            split2(va[2*w], va[2*w+1], hi, lo);
            As[0][lr][wbase + w] = hi;  As[0][lr][8 + wbase + w] = lo;
            split2(vw[2*w], vw[2*w+1], hi, lo);
            Ws[0][lr][wbase + w] = hi;  Ws[0][lr][8 + wbase + w] = lo;
        }
    }
    __syncthreads();

    int bsel = 0;
    for (int k0 = 0; k0 < EMB; k0 += 16) {
        const bool more = (k0 + 16) < EMB;
        if (more) {
            pa0 = *(const float4*)(Ap + k0 + 16);
            pa1 = *(const float4*)(Ap + k0 + 20);
            pw0 = *(const float4*)(Wp + k0 + 16);
            pw1 = *(const float4*)(Wp + k0 + 20);
        }

        uint32_t ah[2][4], al[2][4];
        #pragma unroll
        for (int mt = 0; mt < 2; mt++) {
            const int mr = warp_m * 32 + mt * 16;
            ah[mt][0] = As[bsel][mr + g    ][tig    ];
            ah[mt][1] = As[bsel][mr + g + 8][tig    ];
            ah[mt][2] = As[bsel][mr + g    ][tig + 4];
            ah[mt][3] = As[bsel][mr + g + 8][tig + 4];
            al[mt][0] = As[bsel][mr + g    ][8 + tig    ];
            al[mt][1] = As[bsel][mr + g + 8][8 + tig    ];
            al[mt][2] = As[bsel][mr + g    ][8 + tig + 4];
            al[mt][3] = As[bsel][mr + g + 8][8 + tig + 4];
        }
        #pragma unroll
        for (int nt = 0; nt < 8; nt++) {
            const int nr = warp_n * 64 + nt * 8 + g;
            uint32_t bh[2] = { Ws[bsel][nr][tig], Ws[bsel][nr][tig + 4] };
            uint32_t bl[2] = { Ws[bsel][nr][8 + tig], Ws[bsel][nr][8 + tig + 4] };
            #pragma unroll
            for (int mt = 0; mt < 2; mt++) {
                mma_bf16_k16(acc[mt][nt], ah[mt], bh);
                mma_bf16_k16(acc[mt][nt], ah[mt], bl);
                mma_bf16_k16(acc[mt][nt], al[mt], bh);
            }
        }

        if (more) {
            const int nb = bsel ^ 1;
            float va[8] = {pa0.x,pa0.y,pa0.z,pa0.w,pa1.x,pa1.y,pa1.z,pa1.w};
            float vw[8] = {pw0.x,pw0.y,pw0.z,pw0.w,pw1.x,pw1.y,pw1.z,pw1.w};
            #pragma unroll
            for (int w = 0; w < 4; w++) {
                uint32_t hi, lo;
                split2(va[2*w], va[2*w+1], hi, lo);
                As[nb][lr][wbase + w] = hi;  As[nb][lr][8 + wbase + w] = lo;
                split2(vw[2*w], vw[2*w+1], hi, lo);
                Ws[nb][lr][wbase + w] = hi;  Ws[nb][lr][8 + wbase + w] = lo;
            }
            __syncthreads();
            bsel = nb;
        }
    }

    #pragma unroll
    for (int mt = 0; mt < 2; mt++) {
        const int r0 = m0 + warp_m * 32 + mt * 16 + g;
        #pragma unroll
        for (int nt = 0; nt < 8; nt++) {
            const int col = n0 + warp_n * 64 + nt * 8 + 2 * tig;
            const float b0 = bias[col], b1 = bias[col + 1];
            float v00 = acc[mt][nt][0] + b0, v01 = acc[mt][nt][1] + b1;
            float v10 = acc[mt][nt][2] + b0, v11 = acc[mt][nt][3] + b1;
            if constexpr (sizeof(OutT) == 4) {
                *(float2*)&C[(size_t)r0 * EMB + col]       = make_float2(v00, v01);
                *(float2*)&C[(size_t)(r0 + 8) * EMB + col] = make_float2(v10, v11);
            } else {
                __half2 h0 = __floats2half2_rn(v00, v01);
                __half2 h1 = __floats2half2_rn(v10, v11);
                *(uint32_t*)&C[(size_t)r0 * EMB + col]       = *(uint32_t*)&h0;
                *(uint32_t*)&C[(size_t)(r0 + 8) * EMB + col] = *(uint32_t*)&h1;
            }
        }
    }
}

// ---------------------------------------------------------------------------
// Flash attention, fp16 tensor path.
// 128 threads (4 warps), 64 q rows/block, 64-key tiles, double-buffered
// cp.async K/V (fp16), ldmatrix fragments, register softmax, fp16 P.
// ---------------------------------------------------------------------------
#define HROW  72                  // smem row stride (halfs)
#define ROWB  144                 // smem row stride (bytes)
#define TILEB (64 * ROWB)         // 9216 bytes per tile buffer

__global__ void __launch_bounds__(128) attn_mma_kernel()
{
    extern __shared__ char smraw[];
    __half* Qs   = (__half*)smraw;                    // 64 x HROW
    char*   kv0  = smraw + TILEB;                     // buf0: K,V ; buf1: K,V

    const int tid  = threadIdx.x;
    const int lane = tid & 31;
    const int warp = tid >> 5;
    const int g    = lane >> 2;
    const int tig  = lane & 3;
    const int qrow = warp * 16;

    const int bh = blockIdx.y;
    const int b  = bh >> 4;
    const int h  = bh & 15;
    const int n0 = blockIdx.x << 6;
    const size_t rowbase = (size_t)b * NSEQ;
    const int    coloff  = h * HD;

    const __half* Qg = g_qh + (rowbase + n0) * EMB + coloff;
    const __half* Kg = g_kh + rowbase * EMB + coloff;
    const __half* Vg = g_vh + rowbase * EMB + coloff;

    // per-thread cp.async coords: 512 16B-chunks per tile, 4 per thread
    // idx = tid + i*128 ; r = idx>>3 ; ch = idx&7
    // ---- prologue: issue K0/V0 loads ----
    {
        char* kb = kv0;
        char* vb = kv0 + TILEB;
        #pragma unroll
        for (int i = 0; i < 4; i++) {
            const int idx = tid + i * 128;
            const int r = idx >> 3, ch = idx & 7;
            asm volatile("cp.async.cg.shared.global [%0], [%1], 16;\n" ::
                "r"(smem_u32(kb + r * ROWB + ch * 16)),
                "l"(Kg + (size_t)r * EMB + ch * 8));
            asm volatile("cp.async.cg.shared.global [%0], [%1], 16;\n" ::
                "r"(smem_u32(vb + r * ROWB + ch * 16)),
                "l"(Vg + (size_t)r * EMB + ch * 8));
        }
        asm volatile("cp.async.commit_group;\n");
    }

    // ---- stage Q ----
    #pragma unroll
    for (int i = 0; i < 4; i++) {
        const int idx = tid + i * 128;
        const int r = idx >> 3, ch = idx & 7;
        *(int4*)((char*)Qs + r * ROWB + ch * 16) =
            *(const int4*)(Qg + (size_t)r * EMB + ch * 8);
    }
    __syncthreads();

    // Q fragments (fp16 pairs): qf[ks][4], ks = k16 chunk 0..3
    uint32_t qf[4][4];
    {
        const int row  = qrow + (lane & 15);
        const int kofb = (lane & 16) ? 8 : 0;
        #pragma unroll
        for (int ks = 0; ks < 4; ks++) {
            uint32_t addr = smem_u32((char*)Qs + row * ROWB + (ks * 16 + kofb) * 2);
            ldsm_x4(qf[ks], addr);
        }
    }

    float of[8][4];
    #pragma unroll
    for (int dt = 0; dt < 8; dt++)
        #pragma unroll
        for (int i = 0; i < 4; i++) of[dt][i] = 0.f;

    float m0 = -1e30f, m1 = -1e30f, l0 = 0.f, l1 = 0.f;

    // ldmatrix lane address components
    const int krow_l = (lane & 7);                    // within 8-row group
    const int kcol_l = (lane >> 3) * 8;               // 0,8,16,24 (K B-frags)
    const int vrow_l = ((lane & 8) ? 8 : 0) + (lane & 7);  // key within 16
    const int vcol_l = (lane & 16) ? 8 : 0;           // dim half (V trans)

    const int NT = NSEQ / 64;
    for (int t = 0; t < NT; t++) {
        char* kb = kv0 + (t & 1) * 2 * TILEB;
        char* vb = kb + TILEB;

        asm volatile("cp.async.wait_group 0;\n" ::: "memory");
        __syncthreads();

        if (t + 1 < NT) {
            char* kn = kv0 + ((t + 1) & 1) * 2 * TILEB;
            char* vn = kn + TILEB;
            const size_t gofs = (size_t)(t + 1) * 64 * EMB;
            #pragma unroll
            for (int i = 0; i < 4; i++) {
                const int idx = tid + i * 128;
                const int r = idx >> 3, ch = idx & 7;
                asm volatile("cp.async.cg.shared.global [%0], [%1], 16;\n" ::
                    "r"(smem_u32(kn + r * ROWB + ch * 16)),
                    "l"(Kg + gofs + (size_t)r * EMB + ch * 8));
                asm volatile("cp.async.cg.shared.global [%0], [%1], 16;\n" ::
                    "r"(smem_u32(vn + r * ROWB + ch * 16)),
                    "l"(Vg + gofs + (size_t)r * EMB + ch * 8));
            }
            asm volatile("cp.async.commit_group;\n");
        }

        // ---- S = Q K^T (fp16 k16) ----
        float sf[8][4];
        #pragma unroll
        for (int nt = 0; nt < 8; nt++)
            #pragma unroll
            for (int i = 0; i < 4; i++) sf[nt][i] = 0.f;

        #pragma unroll
        for (int kh = 0; kh < 2; kh++) {       // k halves: cols 0-31, 32-63
            #pragma unroll
            for (int nt = 0; nt < 8; nt++) {
                uint32_t bf[4];
                uint32_t addr = smem_u32(kb + (nt * 8 + krow_l) * ROWB
                                            + (kh * 32 + kcol_l) * 2);
                ldsm_x4(bf, addr);
                mma_f16_k16(sf[nt], qf[2 * kh    ], bf    );
                mma_f16_k16(sf[nt], qf[2 * kh + 1], bf + 2);
            }
        }

        // ---- register softmax (SCALE applied here) ----
        float mt0 = -1e30f, mt1 = -1e30f;
        #pragma unroll
        for (int nt = 0; nt < 8; nt++) {
            #pragma unroll
            for (int i = 0; i < 4; i++) sf[nt][i] *= SCALE;
            mt0 = fmaxf(mt0, fmaxf(sf[nt][0], sf[nt][1]));
            mt1 = fmaxf(mt1, fmaxf(sf[nt][2], sf[nt][3]));
        }
        mt0 = fmaxf(mt0, __shfl_xor_sync(0xffffffffu, mt0, 1));
        mt0 = fmaxf(mt0, __shfl_xor_sync(0xffffffffu, mt0, 2));
        mt1 = fmaxf(mt1, __shfl_xor_sync(0xffffffffu, mt1, 1));
        mt1 = fmaxf(mt1, __shfl_xor_sync(0xffffffffu, mt1, 2));

        const float mn0 = fmaxf(m0, mt0);
        const float mn1 = fmaxf(m1, mt1);
        const float c0 = __expf(m0 - mn0);
        const float c1 = __expf(m1 - mn1);
        m0 = mn0; m1 = mn1;

        float s0 = 0.f, s1 = 0.f;
        uint32_t pf[4][4];
        #pragma unroll
        for (int kc = 0; kc < 4; kc++) {
            #pragma unroll
            for (int hh = 0; hh < 2; hh++) {
                const int nt = 2 * kc + hh;
                float p0 = __expf(sf[nt][0] - mn0);
                float p1 = __expf(sf[nt][1] - mn0);
                float p2 = __expf(sf[nt][2] - mn1);
                float p3 = __expf(sf[nt][3] - mn1);
                s0 += p0 + p1;
                s1 += p2 + p3;
                pf[kc][2 * hh    ] = packh(p0, p1);
                pf[kc][2 * hh + 1] = packh(p2, p3);
            }
        }
        s0 += __shfl_xor_sync(0xffffffffu, s0, 1);
        s0 += __shfl_xor_sync(0xffffffffu, s0, 2);
        s1 += __shfl_xor_sync(0xffffffffu, s1, 1);
        s1 += __shfl_xor_sync(0xffffffffu, s1, 2);
        l0 = l0 * c0 + s0;
        l1 = l1 * c1 + s1;

        #pragma unroll
        for (int dt = 0; dt < 8; dt++) {
            of[dt][0] *= c0; of[dt][1] *= c0;
            of[dt][2] *= c1; of[dt][3] *= c1;
        }

        // ---- O += P V (fp16, V via ldmatrix.trans) ----
        #pragma unroll
        for (int kc = 0; kc < 4; kc++) {
            #pragma unroll
            for (int dp = 0; dp < 4; dp++) {   // dim pairs: dt = 2*dp, 2*dp+1
                uint32_t bv[4];
                uint32_t addr = smem_u32(vb + (kc * 16 + vrow_l) * ROWB
                                            + (dp * 16 + vcol_l) * 2);
                ldsm_x4_t(bv, addr);
                mma_f16_k16(of[2 * dp    ], pf[kc], bv    );
                mma_f16_k16(of[2 * dp + 1], pf[kc], bv + 2);
            }
        }
    }

    // ---- epilogue: normalize, write fp32 ----
    const float li0 = 1.f / l0;
    const float li1 = 1.f / l1;
    const size_t r0 = (rowbase + n0 + qrow + g) * EMB + coloff;
    const size_t r1 = r0 + (size_t)8 * EMB;
    #pragma unroll
    for (int dt = 0; dt < 8; dt++) {
        const int col = dt * 8 + 2 * tig;
        float2 o0 = { of[dt][0] * li0, of[dt][1] * li0 };
        float2 o1 = { of[dt][2] * li1, of[dt][3] * li1 };
        *(float2*)&g_a[r0 + col] = o0;
        *(float2*)&g_a[r1 + col] = o1;
    }
}

// ---------------------------------------------------------------------------
// Launch
// ---------------------------------------------------------------------------
extern "C" void kernel_launch(void* const* d_in, const int* in_sizes, int n_in,
                              void* d_out, int out_size)
{
    const float* x  = (const float*)d_in[0];
    const float* Wq = (const float*)d_in[1];
    const float* bq = (const float*)d_in[2];
    const float* Wk = (const float*)d_in[3];
    const float* bk = (const float*)d_in[4];
    const float* Wv = (const float*)d_in[5];
    const float* bv = (const float*)d_in[6];
    const float* Wo = (const float*)d_in[7];
    const float* bo = (const float*)d_in[8];
    float* out = (float*)d_out;

    __half *qh, *kh, *vh;
    float *a;
    cudaGetSymbolAddress((void**)&qh, g_qh);
    cudaGetSymbolAddress((void**)&kh, g_kh);
    cudaGetSymbolAddress((void**)&vh, g_vh);
    cudaGetSymbolAddress((void**)&a, g_a);

    const int ATTN_SMEM = 5 * TILEB;   // Q + 2*(K+V)
    cudaFuncSetAttribute(attn_mma_kernel, cudaFuncAttributeMaxDynamicSharedMemorySize,
                         ATTN_SMEM);

    dim3 gemm_grid(EMB / 128, MROWS / 128);   // (8, 32)
    gemm_bias_split_kernel<__half><<<gemm_grid, 256>>>(x, Wq, bq, qh);
    gemm_bias_split_kernel<__half><<<gemm_grid, 256>>>(x, Wk, bk, kh);
    gemm_bias_split_kernel<__half><<<gemm_grid, 256>>>(x, Wv, bv, vh);

    dim3 attn_grid(NSEQ / 64, BATCH * NH);    // (32, 32)
    attn_mma_kernel<<<attn_grid, 128, ATTN_SMEM>>>();

    gemm_bias_split_kernel<float><<<gemm_grid, 256>>>(a, Wo, bo, out);
}

// round 5
// speedup vs baseline: 7.1010x; 2.1211x over previous
#include <cuda_runtime.h>
#include <cuda_fp16.h>
#include <cstdint>

#define NSEQ   2048
#define EMB    1024
#define NH     16
#define HD     64
#define BATCH  2
#define MROWS  (BATCH * NSEQ)   // 4096
#define SCALE  0.125f           // 1/sqrt(64)

// Scratch (__device__ globals, allocation-free rule).
__device__ __half g_xh[MROWS * EMB];   // x in fp16
__device__ __half g_wq[EMB * EMB];
__device__ __half g_wk[EMB * EMB];
__device__ __half g_wv[EMB * EMB];
__device__ __half g_wo[EMB * EMB];
__device__ __half g_qh[MROWS * EMB];
__device__ __half g_kh[MROWS * EMB];
__device__ __half g_vh[MROWS * EMB];
__device__ __half g_ah[MROWS * EMB];

// ---------------------------------------------------------------------------
// helpers
// ---------------------------------------------------------------------------
__device__ __forceinline__ void mma_f16_k16(float* c, const uint32_t* a, const uint32_t* b)
{
    asm volatile(
        "mma.sync.aligned.m16n8k16.row.col.f32.f16.f16.f32 "
        "{%0,%1,%2,%3}, {%4,%5,%6,%7}, {%8,%9}, {%0,%1,%2,%3};\n"
        : "+f"(c[0]), "+f"(c[1]), "+f"(c[2]), "+f"(c[3])
        : "r"(a[0]), "r"(a[1]), "r"(a[2]), "r"(a[3]), "r"(b[0]), "r"(b[1]));
}

__device__ __forceinline__ void ldsm_x4(uint32_t* r, uint32_t addr)
{
    asm volatile("ldmatrix.sync.aligned.m8n8.x4.shared.b16 {%0,%1,%2,%3}, [%4];"
        : "=r"(r[0]), "=r"(r[1]), "=r"(r[2]), "=r"(r[3]) : "r"(addr));
}

__device__ __forceinline__ void ldsm_x4_t(uint32_t* r, uint32_t addr)
{
    asm volatile("ldmatrix.sync.aligned.m8n8.x4.trans.shared.b16 {%0,%1,%2,%3}, [%4];"
        : "=r"(r[0]), "=r"(r[1]), "=r"(r[2]), "=r"(r[3]) : "r"(addr));
}

__device__ __forceinline__ uint32_t packh(float lo, float hi)
{
    __half2 h = __floats2half2_rn(lo, hi);
    return *reinterpret_cast<uint32_t*>(&h);
}

__device__ __forceinline__ uint32_t smem_u32(const void* p)
{
    return (uint32_t)__cvta_generic_to_shared(p);
}

// ---------------------------------------------------------------------------
// fp32 -> fp16 conversion (vectorized, n multiple of 4)
// ---------------------------------------------------------------------------
__global__ void f2h_kernel(const float* __restrict__ in, __half* __restrict__ out)
{
    const int i = blockIdx.x * blockDim.x + threadIdx.x;
    float4 v = ((const float4*)in)[i];
    __half2 h0 = __floats2half2_rn(v.x, v.y);
    __half2 h1 = __floats2half2_rn(v.z, v.w);
    uint2 u = { *(uint32_t*)&h0, *(uint32_t*)&h1 };
    ((uint2*)out)[i] = u;
}

// ---------------------------------------------------------------------------
// fp16 GEMM: C[4096,1024] = A[4096,1024] @ W[1024,1024]^T + bias
// 128x128x32 tiles, 256 threads, 8 warps (2m x 4n), warp tile 64x32.
// cp.async double-buffered, ldmatrix fragments, padded 40-half rows.
// ---------------------------------------------------------------------------
#define GRS 40   // smem row stride in halfs (80B -> conflict-free ldsm)

template <typename OutT>
__global__ void __launch_bounds__(256) gemm_f16_kernel(
    const __half* __restrict__ A, const __half* __restrict__ W,
    const float* __restrict__ bias, OutT* __restrict__ C)
{
    __shared__ __half Asm[2][128][GRS];
    __shared__ __half Bsm[2][128][GRS];

    const int tid  = threadIdx.x;
    const int lane = tid & 31;
    const int warp = tid >> 5;
    const int g    = lane >> 2;
    const int tig  = lane & 3;
    const int warp_m = warp & 1;      // 0..1 -> 64 rows
    const int warp_n = warp >> 1;     // 0..3 -> 32 cols
    const int m0 = blockIdx.y << 7;
    const int n0 = blockIdx.x << 7;

    float acc[4][4][4];
    #pragma unroll
    for (int mi = 0; mi < 4; mi++)
        #pragma unroll
        for (int ni = 0; ni < 4; ni++)
            #pragma unroll
            for (int i = 0; i < 4; i++) acc[mi][ni][i] = 0.f;

    // cp.async: 512 16B chunks per operand per stage; 2 per thread.
    // idx = tid + i*256: row = idx>>2, chunk = (idx&3)*8 halfs
    const int lrow = tid >> 2;
    const int lch  = (tid & 3) << 3;
    const __half* Ag = A + (size_t)(m0 + lrow) * EMB + lch;
    const __half* Bg = W + (size_t)(n0 + lrow) * EMB + lch;
    const __half* Ag2 = Ag + (size_t)64 * EMB;
    const __half* Bg2 = Bg + (size_t)64 * EMB;

    auto load_stage = [&](int s, int k0) {
        asm volatile("cp.async.cg.shared.global [%0], [%1], 16;\n" ::
            "r"(smem_u32(&Asm[s][lrow][lch])), "l"(Ag + k0));
        asm volatile("cp.async.cg.shared.global [%0], [%1], 16;\n" ::
            "r"(smem_u32(&Asm[s][lrow + 64][lch])), "l"(Ag2 + k0));
        asm volatile("cp.async.cg.shared.global [%0], [%1], 16;\n" ::
            "r"(smem_u32(&Bsm[s][lrow][lch])), "l"(Bg + k0));
        asm volatile("cp.async.cg.shared.global [%0], [%1], 16;\n" ::
            "r"(smem_u32(&Bsm[s][lrow + 64][lch])), "l"(Bg2 + k0));
        asm volatile("cp.async.commit_group;\n");
    };

    load_stage(0, 0);

    const int arow = warp_m * 64 + (lane & 15);
    const int acol = (lane >> 4) << 3;
    const int brow = warp_n * 32 + (lane & 7);
    const int bcol = (lane >> 3) << 3;

    for (int it = 0; it < EMB / 32; it++) {
        const int s = it & 1;
        asm volatile("cp.async.wait_group 0;\n" ::: "memory");
        __syncthreads();
        if (it + 1 < EMB / 32) load_stage(s ^ 1, (it + 1) * 32);

        // B fragments: one ldsm.x4 per n8 covers full k32
        uint32_t bf[4][4];
        #pragma unroll
        for (int ni = 0; ni < 4; ni++)
            ldsm_x4(bf[ni], smem_u32(&Bsm[s][brow + ni * 8][bcol]));

        #pragma unroll
        for (int kk = 0; kk < 2; kk++) {
            uint32_t af[4][4];
            #pragma unroll
            for (int mi = 0; mi < 4; mi++)
                ldsm_x4(af[mi], smem_u32(&Asm[s][arow + mi * 16][kk * 16 + acol]));
            #pragma unroll
            for (int mi = 0; mi < 4; mi++)
                #pragma unroll
                for (int ni = 0; ni < 4; ni++)
                    mma_f16_k16(acc[mi][ni], af[mi], bf[ni] + 2 * kk);
        }
    }

    // epilogue
    #pragma unroll
    for (int mi = 0; mi < 4; mi++) {
        const int r0 = m0 + warp_m * 64 + mi * 16 + g;
        #pragma unroll
        for (int ni = 0; ni < 4; ni++) {
            const int col = n0 + warp_n * 32 + ni * 8 + 2 * tig;
            const float b0 = bias[col], b1 = bias[col + 1];
            float v00 = acc[mi][ni][0] + b0, v01 = acc[mi][ni][1] + b1;
            float v10 = acc[mi][ni][2] + b0, v11 = acc[mi][ni][3] + b1;
            if constexpr (sizeof(OutT) == 4) {
                *(float2*)&C[(size_t)r0 * EMB + col]       = make_float2(v00, v01);
                *(float2*)&C[(size_t)(r0 + 8) * EMB + col] = make_float2(v10, v11);
            } else {
                __half2 h0 = __floats2half2_rn(v00, v01);
                __half2 h1 = __floats2half2_rn(v10, v11);
                *(uint32_t*)&C[(size_t)r0 * EMB + col]       = *(uint32_t*)&h0;
                *(uint32_t*)&C[(size_t)(r0 + 8) * EMB + col] = *(uint32_t*)&h1;
            }
        }
    }
}

// ---------------------------------------------------------------------------
// Flash attention, fp16 tensor path (unchanged from R4 except fp16 output).
// ---------------------------------------------------------------------------
#define HROW  72
#define ROWB  144
#define TILEB (64 * ROWB)

__global__ void __launch_bounds__(128) attn_mma_kernel()
{
    extern __shared__ char smraw[];
    __half* Qs  = (__half*)smraw;
    char*   kv0 = smraw + TILEB;

    const int tid  = threadIdx.x;
    const int lane = tid & 31;
    const int warp = tid >> 5;
    const int g    = lane >> 2;
    const int tig  = lane & 3;
    const int qrow = warp * 16;

    const int bh = blockIdx.y;
    const int b  = bh >> 4;
    const int h  = bh & 15;
    const int n0 = blockIdx.x << 6;
    const size_t rowbase = (size_t)b * NSEQ;
    const int    coloff  = h * HD;

    const __half* Qg = g_qh + (rowbase + n0) * EMB + coloff;
    const __half* Kg = g_kh + rowbase * EMB + coloff;
    const __half* Vg = g_vh + rowbase * EMB + coloff;

    {
        char* kb = kv0;
        char* vb = kv0 + TILEB;
        #pragma unroll
        for (int i = 0; i < 4; i++) {
            const int idx = tid + i * 128;
            const int r = idx >> 3, ch = idx & 7;
            asm volatile("cp.async.cg.shared.global [%0], [%1], 16;\n" ::
                "r"(smem_u32(kb + r * ROWB + ch * 16)),
                "l"(Kg + (size_t)r * EMB + ch * 8));
            asm volatile("cp.async.cg.shared.global [%0], [%1], 16;\n" ::
                "r"(smem_u32(vb + r * ROWB + ch * 16)),
                "l"(Vg + (size_t)r * EMB + ch * 8));
        }
        asm volatile("cp.async.commit_group;\n");
    }

    #pragma unroll
    for (int i = 0; i < 4; i++) {
        const int idx = tid + i * 128;
        const int r = idx >> 3, ch = idx & 7;
        *(int4*)((char*)Qs + r * ROWB + ch * 16) =
            *(const int4*)(Qg + (size_t)r * EMB + ch * 8);
    }
    __syncthreads();

    uint32_t qf[4][4];
    {
        const int row  = qrow + (lane & 15);
        const int kofb = (lane & 16) ? 8 : 0;
        #pragma unroll
        for (int ks = 0; ks < 4; ks++)
            ldsm_x4(qf[ks], smem_u32((char*)Qs + row * ROWB + (ks * 16 + kofb) * 2));
    }

    float of[8][4];
    #pragma unroll
    for (int dt = 0; dt < 8; dt++)
        #pragma unroll
        for (int i = 0; i < 4; i++) of[dt][i] = 0.f;

    float m0 = -1e30f, m1 = -1e30f, l0 = 0.f, l1 = 0.f;

    const int krow_l = (lane & 7);
    const int kcol_l = (lane >> 3) * 8;
    const int vrow_l = ((lane & 8) ? 8 : 0) + (lane & 7);
    const int vcol_l = (lane & 16) ? 8 : 0;

    const int NT = NSEQ / 64;
    for (int t = 0; t < NT; t++) {
        char* kb = kv0 + (t & 1) * 2 * TILEB;
        char* vb = kb + TILEB;

        asm volatile("cp.async.wait_group 0;\n" ::: "memory");
        __syncthreads();

        if (t + 1 < NT) {
            char* kn = kv0 + ((t + 1) & 1) * 2 * TILEB;
            char* vn = kn + TILEB;
            const size_t gofs = (size_t)(t + 1) * 64 * EMB;
            #pragma unroll
            for (int i = 0; i < 4; i++) {
                const int idx = tid + i * 128;
                const int r = idx >> 3, ch = idx & 7;
                asm volatile("cp.async.cg.shared.global [%0], [%1], 16;\n" ::
                    "r"(smem_u32(kn + r * ROWB + ch * 16)),
                    "l"(Kg + gofs + (size_t)r * EMB + ch * 8));
                asm volatile("cp.async.cg.shared.global [%0], [%1], 16;\n" ::
                    "r"(smem_u32(vn + r * ROWB + ch * 16)),
                    "l"(Vg + gofs + (size_t)r * EMB + ch * 8));
            }
            asm volatile("cp.async.commit_group;\n");
        }

        float sf[8][4];
        #pragma unroll
        for (int nt = 0; nt < 8; nt++)
            #pragma unroll
            for (int i = 0; i < 4; i++) sf[nt][i] = 0.f;

        #pragma unroll
        for (int kh = 0; kh < 2; kh++) {
            #pragma unroll
            for (int nt = 0; nt < 8; nt++) {
                uint32_t bf[4];
                ldsm_x4(bf, smem_u32(kb + (nt * 8 + krow_l) * ROWB
                                        + (kh * 32 + kcol_l) * 2));
                mma_f16_k16(sf[nt], qf[2 * kh    ], bf    );
                mma_f16_k16(sf[nt], qf[2 * kh + 1], bf + 2);
            }
        }

        float mt0 = -1e30f, mt1 = -1e30f;
        #pragma unroll
        for (int nt = 0; nt < 8; nt++) {
            #pragma unroll
            for (int i = 0; i < 4; i++) sf[nt][i] *= SCALE;
            mt0 = fmaxf(mt0, fmaxf(sf[nt][0], sf[nt][1]));
            mt1 = fmaxf(mt1, fmaxf(sf[nt][2], sf[nt][3]));
        }
        mt0 = fmaxf(mt0, __shfl_xor_sync(0xffffffffu, mt0, 1));
        mt0 = fmaxf(mt0, __shfl_xor_sync(0xffffffffu, mt0, 2));
        mt1 = fmaxf(mt1, __shfl_xor_sync(0xffffffffu, mt1, 1));
        mt1 = fmaxf(mt1, __shfl_xor_sync(0xffffffffu, mt1, 2));

        const float mn0 = fmaxf(m0, mt0);
        const float mn1 = fmaxf(m1, mt1);
        const float c0 = __expf(m0 - mn0);
        const float c1 = __expf(m1 - mn1);
        m0 = mn0; m1 = mn1;

        float s0 = 0.f, s1 = 0.f;
        uint32_t pf[4][4];
        #pragma unroll
        for (int kc = 0; kc < 4; kc++) {
            #pragma unroll
            for (int hh = 0; hh < 2; hh++) {
                const int nt = 2 * kc + hh;
                float p0 = __expf(sf[nt][0] - mn0);
                float p1 = __expf(sf[nt][1] - mn0);
                float p2 = __expf(sf[nt][2] - mn1);
                float p3 = __expf(sf[nt][3] - mn1);
                s0 += p0 + p1;
                s1 += p2 + p3;
                pf[kc][2 * hh    ] = packh(p0, p1);
                pf[kc][2 * hh + 1] = packh(p2, p3);
            }
        }
        s0 += __shfl_xor_sync(0xffffffffu, s0, 1);
        s0 += __shfl_xor_sync(0xffffffffu, s0, 2);
        s1 += __shfl_xor_sync(0xffffffffu, s1, 1);
        s1 += __shfl_xor_sync(0xffffffffu, s1, 2);
        l0 = l0 * c0 + s0;
        l1 = l1 * c1 + s1;

        #pragma unroll
        for (int dt = 0; dt < 8; dt++) {
            of[dt][0] *= c0; of[dt][1] *= c0;
            of[dt][2] *= c1; of[dt][3] *= c1;
        }

        #pragma unroll
        for (int kc = 0; kc < 4; kc++) {
            #pragma unroll
            for (int dp = 0; dp < 4; dp++) {
                uint32_t bv[4];
                ldsm_x4_t(bv, smem_u32(vb + (kc * 16 + vrow_l) * ROWB
                                          + (dp * 16 + vcol_l) * 2));
                mma_f16_k16(of[2 * dp    ], pf[kc], bv    );
                mma_f16_k16(of[2 * dp + 1], pf[kc], bv + 2);
            }
        }
    }

    // epilogue: normalize, write fp16
    const float li0 = 1.f / l0;
    const float li1 = 1.f / l1;
    const size_t r0 = (rowbase + n0 + qrow + g) * EMB + coloff;
    const size_t r1 = r0 + (size_t)8 * EMB;
    #pragma unroll
    for (int dt = 0; dt < 8; dt++) {
        const int col = dt * 8 + 2 * tig;
        *(uint32_t*)&g_ah[r0 + col] = packh(of[dt][0] * li0, of[dt][1] * li0);
        *(uint32_t*)&g_ah[r1 + col] = packh(of[dt][2] * li1, of[dt][3] * li1);
    }
}

// ---------------------------------------------------------------------------
// Launch
// ---------------------------------------------------------------------------
extern "C" void kernel_launch(void* const* d_in, const int* in_sizes, int n_in,
                              void* d_out, int out_size)
{
    const float* x  = (const float*)d_in[0];
    const float* Wq = (const float*)d_in[1];
    const float* bq = (const float*)d_in[2];
    const float* Wk = (const float*)d_in[3];
    const float* bk = (const float*)d_in[4];
    const float* Wv = (const float*)d_in[5];
    const float* bv = (const float*)d_in[6];
    const float* Wo = (const float*)d_in[7];
    const float* bo = (const float*)d_in[8];
    float* out = (float*)d_out;

    __half *xh, *wq, *wk, *wv, *wo, *qh, *kh, *vh, *ah;
    cudaGetSymbolAddress((void**)&xh, g_xh);
    cudaGetSymbolAddress((void**)&wq, g_wq);
    cudaGetSymbolAddress((void**)&wk, g_wk);
    cudaGetSymbolAddress((void**)&wv, g_wv);
    cudaGetSymbolAddress((void**)&wo, g_wo);
    cudaGetSymbolAddress((void**)&qh, g_qh);
    cudaGetSymbolAddress((void**)&kh, g_kh);
    cudaGetSymbolAddress((void**)&vh, g_vh);
    cudaGetSymbolAddress((void**)&ah, g_ah);

    const int ATTN_SMEM = 5 * TILEB;
    cudaFuncSetAttribute(attn_mma_kernel, cudaFuncAttributeMaxDynamicSharedMemorySize,
                         ATTN_SMEM);

    // fp32 -> fp16 conversions
    f2h_kernel<<<(MROWS * EMB / 4) / 256, 256>>>(x,  xh);
    f2h_kernel<<<(EMB * EMB / 4) / 256, 256>>>(Wq, wq);
    f2h_kernel<<<(EMB * EMB / 4) / 256, 256>>>(Wk, wk);
    f2h_kernel<<<(EMB * EMB / 4) / 256, 256>>>(Wv, wv);
    f2h_kernel<<<(EMB * EMB / 4) / 256, 256>>>(Wo, wo);

    dim3 gemm_grid(EMB / 128, MROWS / 128);   // (8, 32)
    gemm_f16_kernel<__half><<<gemm_grid, 256>>>(xh, wq, bq, qh);
    gemm_f16_kernel<__half><<<gemm_grid, 256>>>(xh, wk, bk, kh);
    gemm_f16_kernel<__half><<<gemm_grid, 256>>>(xh, wv, bv, vh);

    dim3 attn_grid(NSEQ / 64, BATCH * NH);    // (32, 32)
    attn_mma_kernel<<<attn_grid, 128, ATTN_SMEM>>>();

    gemm_f16_kernel<float><<<gemm_grid, 256>>>(ah, wo, bo, out);
}